// round 9
// baseline (speedup 1.0000x reference)
#include <cuda_runtime.h>
#include <cuda_fp16.h>
#include <cstdint>

#define SEQ 4096
#define HD 64
#define NBATCH 4
#define TQ 128
#define TN 128
#define NIT 32
#define NTH 512
#define CEXP 0.18033688011112042f  // log2(e)/temperature(8)

// padded smem strides (in halves)
#define KSTR 72    // K/V tiles: 64 cols -> 144B rows
#define PSTR 136   // P tile: 128 cols -> 272B rows

// smem half-offsets
#define H_P0 0               // P buf 0 (Q staged here in prologue): 128*136 = 17408
#define H_P1 17408           // P buf 1
#define H_K 34816            // 4 rings of 128*72 = 9216
#define H_V 71680            // 4 rings of 9216
#define H_TOT 108544
#define SMEM_BYTES (H_TOT * 2 + 128 * 4)  // + RS

__device__ __half g_QH[NBATCH * SEQ * HD];
__device__ __half g_KH[NBATCH * SEQ * HD];
__device__ __half g_VH[NBATCH * SEQ * HD];

__device__ __forceinline__ uint32_t f2h2(float x, float y) {
    __half2 h = __floats2half2_rn(x, y);
    return *reinterpret_cast<uint32_t*>(&h);
}
__device__ __forceinline__ void ldsm4(uint32_t& r0, uint32_t& r1, uint32_t& r2,
                                      uint32_t& r3, uint32_t addr) {
    asm volatile("ldmatrix.sync.aligned.m8n8.x4.shared.b16 {%0,%1,%2,%3}, [%4];"
                 : "=r"(r0), "=r"(r1), "=r"(r2), "=r"(r3) : "r"(addr));
}
__device__ __forceinline__ void ldsm4t(uint32_t& r0, uint32_t& r1, uint32_t& r2,
                                       uint32_t& r3, uint32_t addr) {
    asm volatile("ldmatrix.sync.aligned.m8n8.x4.trans.shared.b16 {%0,%1,%2,%3}, [%4];"
                 : "=r"(r0), "=r"(r1), "=r"(r2), "=r"(r3) : "r"(addr));
}
__device__ __forceinline__ void mma16(float c[4], const uint32_t a[4], uint32_t b0,
                                      uint32_t b1) {
    asm volatile(
        "mma.sync.aligned.m16n8k16.row.col.f32.f16.f16.f32 "
        "{%0,%1,%2,%3}, {%4,%5,%6,%7}, {%8,%9}, {%0,%1,%2,%3};\n"
        : "+f"(c[0]), "+f"(c[1]), "+f"(c[2]), "+f"(c[3])
        : "r"(a[0]), "r"(a[1]), "r"(a[2]), "r"(a[3]), "r"(b0), "r"(b1));
}
__device__ __forceinline__ void mma16_z(float d[4], const uint32_t a[4], uint32_t b0,
                                        uint32_t b1) {
    asm volatile(
        "mma.sync.aligned.m16n8k16.row.col.f32.f16.f16.f32 "
        "{%0,%1,%2,%3}, {%4,%5,%6,%7}, {%8,%9}, {%10,%10,%10,%10};\n"
        : "=f"(d[0]), "=f"(d[1]), "=f"(d[2]), "=f"(d[3])
        : "r"(a[0]), "r"(a[1]), "r"(a[2]), "r"(a[3]), "r"(b0), "r"(b1), "f"(0.f));
}
__device__ __forceinline__ void cpa16(uint32_t dst, const __half* src) {
    asm volatile("cp.async.cg.shared.global [%0], [%1], 16;" ::"r"(dst), "l"(src));
}
#define CP_COMMIT() asm volatile("cp.async.commit_group;" ::: "memory")
#define CP_WAIT(n) asm volatile("cp.async.wait_group %0;" ::"n"(n) : "memory")

// ---- pre-pass: fp32 -> fp16 for Q, K, V ----
__global__ void __launch_bounds__(256) cvt_kernel(const float* __restrict__ q,
                                                  const float* __restrict__ k,
                                                  const float* __restrict__ v) {
    int i = (blockIdx.x * 256 + threadIdx.x) * 4;
    float4 a = *reinterpret_cast<const float4*>(q + i);
    float4 bk = *reinterpret_cast<const float4*>(k + i);
    float4 c = *reinterpret_cast<const float4*>(v + i);
    *reinterpret_cast<uint2*>(&g_QH[i]) = make_uint2(f2h2(a.x, a.y), f2h2(a.z, a.w));
    *reinterpret_cast<uint2*>(&g_KH[i]) = make_uint2(f2h2(bk.x, bk.y), f2h2(bk.z, bk.w));
    *reinterpret_cast<uint2*>(&g_VH[i]) = make_uint2(f2h2(c.x, c.y), f2h2(c.z, c.w));
}

__global__ void __launch_bounds__(NTH, 1)
attn_fused(float* __restrict__ outp, float* __restrict__ attnp) {
    extern __shared__ __half sh[];
    float* RS = reinterpret_cast<float*>(sh + H_TOT);
    const uint32_t smb = (uint32_t)__cvta_generic_to_shared(sh);

    const int tid = threadIdx.x, w = tid >> 5, lane = tid & 31;
    const int g = lane >> 2, tg = lane & 3;
    const int lr3 = lane & 7, b3 = (lane >> 3) & 1, b4 = (lane >> 4) & 1;
    const int b = blockIdx.x >> 5;
    const int q0 = (blockIdx.x & 31) << 7;
    const int wq = (w >> 2) * 32;        // 4 q-groups of 32 rows
    const int wn = (w & 3) * 32;         // 4 n-groups of 32 cols (QK)
    const int wno = (w & 3) * 16;        // AV/out n-slice (16 wide)

    // ldmatrix per-thread offsets (bytes)
    const uint32_t kq_off = (uint32_t)(wn + b4 * 8 + lr3) * 144u + (uint32_t)b3 * 16u;
    const uint32_t pa72 = (uint32_t)(b3 * 8 + lr3) * 144u + (uint32_t)b4 * 16u;   // Q (144B rows)
    const uint32_t pa_off = (uint32_t)(b3 * 8 + lr3) * 272u + (uint32_t)b4 * 16u; // P (272B rows)
    const uint32_t va_off = (uint32_t)(b3 * 8 + lr3) * 144u + (uint32_t)b4 * 16u +
                            (uint32_t)wno * 2u;

    const __half* Qh = g_QH + ((size_t)b * SEQ + q0) * HD;
    const __half* Kh = g_KH + (size_t)b * SEQ * HD;
    const __half* Vh = g_VH + (size_t)b * SEQ * HD;

    if (tid < TQ) RS[tid] = 0.f;

    // stage a 128x64 fp16 tile via cp.async (1024 16B chunks)
    auto stage = [&](uint32_t hbase, const __half* gsrc) {
#pragma unroll
        for (int t = 0; t < 2; ++t) {
            int ci = tid + t * NTH;
            int row = ci >> 3, c8 = ci & 7;
            cpa16(smb + 2u * (uint32_t)(hbase + row * KSTR) + (uint32_t)c8 * 16u,
                  gsrc + row * HD + c8 * 8);
        }
    };

    const uint32_t kB[4] = {smb + 2u * (H_K + 0 * 9216), smb + 2u * (H_K + 1 * 9216),
                            smb + 2u * (H_K + 2 * 9216), smb + 2u * (H_K + 3 * 9216)};
    const uint32_t vB[4] = {smb + 2u * (H_V + 0 * 9216), smb + 2u * (H_V + 1 * 9216),
                            smb + 2u * (H_V + 2 * 9216), smb + 2u * (H_V + 3 * 9216)};

    // ---- prologue: Q + first K tiles ----
    stage(H_P0, Qh);
    CP_COMMIT();
    stage(H_K + 0 * 9216, Kh);
    CP_COMMIT();
    stage(H_K + 1 * 9216, Kh + TN * HD);
    CP_COMMIT();
    CP_WAIT(0);
    __syncthreads();

    // hoist Q fragments (Q staged with 144B rows in P0 region)
    uint32_t qf[4][2][4];
#pragma unroll
    for (int kk = 0; kk < 4; ++kk)
#pragma unroll
        for (int i = 0; i < 2; ++i)
            ldsm4(qf[kk][i][0], qf[kk][i][1], qf[kk][i][2], qf[kk][i][3],
                  smb + (uint32_t)(wq + i * 16) * 144u + pa72 + kk * 32u);

    float c[2][4][4];
    auto qk_issue = [&](uint32_t kbuf) {
#pragma unroll
        for (int kk = 0; kk < 4; ++kk) {
#pragma unroll
            for (int j2 = 0; j2 < 2; ++j2) {
                uint32_t b0, b1, b2_, b3_;
                ldsm4(b0, b1, b2_, b3_, kbuf + kq_off + (uint32_t)j2 * 2304u + kk * 32u);
                if (kk == 0) {
                    mma16_z(c[0][2 * j2], qf[0][0], b0, b1);
                    mma16_z(c[1][2 * j2], qf[0][1], b0, b1);
                    mma16_z(c[0][2 * j2 + 1], qf[0][0], b2_, b3_);
                    mma16_z(c[1][2 * j2 + 1], qf[0][1], b2_, b3_);
                } else {
                    mma16(c[0][2 * j2], qf[kk][0], b0, b1);
                    mma16(c[1][2 * j2], qf[kk][1], b0, b1);
                    mma16(c[0][2 * j2 + 1], qf[kk][0], b2_, b3_);
                    mma16(c[1][2 * j2 + 1], qf[kk][1], b2_, b3_);
                }
            }
        }
    };

    // ================= Phase A: rowsums of exp =================
    float rsum[2][2] = {{0.f, 0.f}, {0.f, 0.f}};
    qk_issue(kB[0]);
    for (int it = 0; it < NIT; ++it) {
        if (it + 2 < NIT) {
            stage(H_K + ((it + 2) & 3) * 9216, Kh + (it + 2) * TN * HD);
            CP_COMMIT();
        }
#pragma unroll
        for (int i = 0; i < 2; ++i)
#pragma unroll
            for (int j = 0; j < 4; ++j) {
                rsum[i][0] += exp2f(c[i][j][0] * CEXP) + exp2f(c[i][j][1] * CEXP);
                rsum[i][1] += exp2f(c[i][j][2] * CEXP) + exp2f(c[i][j][3] * CEXP);
            }
        if (it + 2 < NIT) CP_WAIT(1); else CP_WAIT(0);
        __syncthreads();
        if (it + 1 < NIT) qk_issue(kB[(it + 1) & 3]);
    }
#pragma unroll
    for (int i = 0; i < 2; ++i)
#pragma unroll
        for (int h = 0; h < 2; ++h) {
            float v = rsum[i][h];
            v += __shfl_xor_sync(0xffffffffu, v, 1);
            v += __shfl_xor_sync(0xffffffffu, v, 2);
            if (tg == 0) atomicAdd(&RS[wq + i * 16 + h * 8 + g], v);
        }
    __syncthreads();
    float lr[2][2];
#pragma unroll
    for (int i = 0; i < 2; ++i)
#pragma unroll
        for (int h = 0; h < 2; ++h) lr[i][h] = -log2f(RS[wq + i * 16 + h * 8 + g]);

    // ================= Phase B: attn + AV =================
    float o[2][2][4] = {};
    __syncthreads();
    stage(H_K + 0 * 9216, Kh);
    stage(H_V + 0 * 9216, Vh);
    CP_COMMIT();
    stage(H_K + 1 * 9216, Kh + TN * HD);
    stage(H_V + 1 * 9216, Vh + TN * HD);
    CP_COMMIT();
    CP_WAIT(0);
    __syncthreads();
    qk_issue(kB[0]);

    for (int it = 0; it < NIT; ++it) {
        const int n0 = it * TN;
        // --- pre-barrier: stage(it+2), exp + attn STG + P STS ---
        if (it + 2 < NIT) {
            stage(H_K + ((it + 2) & 3) * 9216, Kh + (it + 2) * TN * HD);
            stage(H_V + ((it + 2) & 3) * 9216, Vh + (it + 2) * TN * HD);
            CP_COMMIT();
        }
        const uint32_t pH = (it & 1) ? H_P1 : H_P0;
#pragma unroll
        for (int i = 0; i < 2; ++i) {
            const int r = wq + i * 16 + g;
            const int row = q0 + r;
            float* ar = attnp + ((size_t)b * SEQ + row) * SEQ + n0 + wn;
#pragma unroll
            for (int j = 0; j < 4; ++j) {
                c[i][j][0] = exp2f(fmaf(c[i][j][0], CEXP, lr[i][0]));
                c[i][j][1] = exp2f(fmaf(c[i][j][1], CEXP, lr[i][0]));
                c[i][j][2] = exp2f(fmaf(c[i][j][2], CEXP, lr[i][1]));
                c[i][j][3] = exp2f(fmaf(c[i][j][3], CEXP, lr[i][1]));
                __stcs(reinterpret_cast<float2*>(ar + j * 8 + 2 * tg),
                       make_float2(c[i][j][0], c[i][j][1]));
                __stcs(reinterpret_cast<float2*>(ar + (size_t)8 * SEQ + j * 8 + 2 * tg),
                       make_float2(c[i][j][2], c[i][j][3]));
                const int col = wn + j * 8 + 2 * tg;
                *reinterpret_cast<uint32_t*>(&sh[pH + r * PSTR + col]) =
                    f2h2(c[i][j][0], c[i][j][1]);
                *reinterpret_cast<uint32_t*>(&sh[pH + (r + 8) * PSTR + col]) =
                    f2h2(c[i][j][2], c[i][j][3]);
            }
        }
        if (it + 2 < NIT) CP_WAIT(1); else CP_WAIT(0);
        __syncthreads();
        // --- post-barrier: next QK, this AV ---
        if (it + 1 < NIT) qk_issue(kB[(it + 1) & 3]);
        const uint32_t pb = smb + 2u * pH;
        const uint32_t vb = vB[it & 3];
#pragma unroll
        for (int kk = 0; kk < 8; ++kk) {
            uint32_t a0[4], a1[4];
            ldsm4(a0[0], a0[1], a0[2], a0[3],
                  pb + (uint32_t)wq * 272u + pa_off + kk * 32u);
            ldsm4(a1[0], a1[1], a1[2], a1[3],
                  pb + (uint32_t)(wq + 16) * 272u + pa_off + kk * 32u);
            uint32_t b0, b1, b2_, b3_;
            ldsm4t(b0, b1, b2_, b3_, vb + kk * 2304u + va_off);
            mma16(o[0][0], a0, b0, b1);
            mma16(o[1][0], a1, b0, b1);
            mma16(o[0][1], a0, b2_, b3_);
            mma16(o[1][1], a1, b2_, b3_);
        }
    }

    // ---- epilogue: write out [B,S,64] ----
#pragma unroll
    for (int i = 0; i < 2; ++i) {
        const int row = q0 + wq + i * 16 + g;
        float* orow = outp + ((size_t)b * SEQ + row) * HD;
#pragma unroll
        for (int j = 0; j < 2; ++j) {
            const int col = wno + j * 8 + 2 * tg;
            *reinterpret_cast<float2*>(orow + col) = make_float2(o[i][j][0], o[i][j][1]);
            *reinterpret_cast<float2*>(orow + 8 * HD + col) =
                make_float2(o[i][j][2], o[i][j][3]);
        }
    }
}

extern "C" void kernel_launch(void* const* d_in, const int* in_sizes, int n_in,
                              void* d_out, int out_size) {
    const float* q = (const float*)d_in[0];
    const float* k = (const float*)d_in[1];
    const float* v = (const float*)d_in[2];
    float* outp = (float*)d_out;
    float* attnp = outp + (size_t)NBATCH * SEQ * HD;

    cvt_kernel<<<NBATCH * SEQ * HD / (256 * 4), 256>>>(q, k, v);

    cudaFuncSetAttribute(attn_fused, cudaFuncAttributeMaxDynamicSharedMemorySize,
                         SMEM_BYTES);
    attn_fused<<<NBATCH * 32, NTH, SMEM_BYTES>>>(outp, attnp);
}